// round 15
// baseline (speedup 1.0000x reference)
#include <cuda_runtime.h>

#define S 2048
#define B 32
#define H 1024

// ---- proj v5: single load-batch per thread, 1024 blocks ----
#define P_TH   256          // 8 warps
#define P_HT   64           // h per block
#define P_KG   4            // k-groups per block
#define P_KSUB 8            // k per group (ONE batch of 8 loads)
#define P_KC   (P_KG * P_KSUB)  // 32 k per block -> 32 k-splits
#define P_BT   16           // b per block -> 2 b-tiles (W read only 2x)

// ---- energy config (R9/R10/R14-proven): 2 rows per warp, 16 warps ----
#define K2_WARPS 16
#define K2_ROWS (K2_WARPS * 2)      // 32 s-rows per block

// Scratch (zero-init at load; softmax re-zeroes g_v each replay).
__device__ float g_v[B * H];        // v[b,h] = sum_k dec[b,k] * W[k,h]
__device__ float g_energy[B * S];   // energies[b,s]

// ---------------------------------------------------------------------------
// v[b,h] += sum_{k in block chunk} dec[b,k] * W[k,h]
// 4 k-groups of 64 threads; partials meet in smem; 1024 atomics per block.
// grid: (H/P_HT, H/P_KC, B/P_BT) = (16, 32, 2) = 1024 blocks of 256 threads.
__global__ __launch_bounds__(P_TH) void proj_kernel(
    const float* __restrict__ dec,   // [B, H]
    const float* __restrict__ W)     // [H, H], W[k*H + h]
{
    __shared__ float s_dec[P_BT][P_KC];          // 2 KB
    __shared__ float s_red[P_KG][P_BT][P_HT];    // 16 KB

    const int tid  = threadIdx.x;
    const int hl   = tid & (P_HT - 1);           // 0..63
    const int g    = tid >> 6;                   // k-group 0..3
    const int h    = blockIdx.x * P_HT + hl;
    const int k0b  = blockIdx.y * P_KC;          // block k base
    const int b0   = blockIdx.z * P_BT;

    // stage dec[b0:b0+16, k0b:k0b+32] -> smem (512 floats, 2 per thread)
    for (int i = tid; i < P_BT * P_KC; i += P_TH) {
        int b = i / P_KC, k = i % P_KC;
        s_dec[b][k] = dec[(b0 + b) * H + k0b + k];
    }
    __syncthreads();

    const int kg = g * P_KSUB;                   // this group's k offset

    // ONE batch of 8 independent loads, then 128 FMAs.
    float w[8];
#pragma unroll
    for (int u = 0; u < 8; u++)
        w[u] = __ldg(&W[(size_t)(k0b + kg + u) * H + h]);

    float acc[P_BT];
#pragma unroll
    for (int b = 0; b < P_BT; b++) acc[b] = 0.0f;
#pragma unroll
    for (int u = 0; u < 8; u++) {
#pragma unroll
        for (int b = 0; b < P_BT; b++)
            acc[b] = fmaf(s_dec[b][kg + u], w[u], acc[b]);
    }

    // partials -> smem
#pragma unroll
    for (int b = 0; b < P_BT; b++)
        s_red[g][b][hl] = acc[b];
    __syncthreads();

    // 1024 (b,h) outputs, 256 threads -> 4 each: 4-way add + one atomic
#pragma unroll
    for (int j = 0; j < 4; j++) {
        int idx = tid + j * P_TH;                // 0..1023
        int b = idx >> 6, hh = idx & (P_HT - 1);
        float sum = s_red[0][b][hh] + s_red[1][b][hh]
                  + s_red[2][b][hh] + s_red[3][b][hh];
        atomicAdd(&g_v[(b0 + b) * H + blockIdx.x * P_HT + hh], sum);
    }
}

// ---------------------------------------------------------------------------
// energies[b,s] = v[b] . enc[s,b,:]   (dominant, streams 256 MB).
// grid: (S/K2_ROWS, B) = (64, 32) = 2048 blocks of 512 threads.
__global__ __launch_bounds__(32 * K2_WARPS) void energy_kernel(
    const float* __restrict__ enc)   // [S, B, H]
{
    __shared__ float4 s_v[H / 4];
    const int b = blockIdx.y;

    const float4* vb = reinterpret_cast<const float4*>(&g_v[b * H]);
    for (int i = threadIdx.x; i < H / 4; i += blockDim.x) s_v[i] = vb[i];
    __syncthreads();

    const int warp = threadIdx.x >> 5;
    const int lane = threadIdx.x & 31;
    const int s0 = blockIdx.x * K2_ROWS + warp;          // row 1
    const int s1 = s0 + K2_WARPS;                        // row 2

    const float4* e0 =
        reinterpret_cast<const float4*>(&enc[((size_t)s0 * B + b) * (size_t)H]);
    const float4* e1 =
        reinterpret_cast<const float4*>(&enc[((size_t)s1 * B + b) * (size_t)H]);

    float acc0 = 0.0f, acc1 = 0.0f;
#pragma unroll
    for (int j = 0; j < (H / 4) / 32; j++) {   // 8 float4 iterations per row
        float4 a = __ldcs(&e0[lane + j * 32]); // streaming: don't pollute L2
        float4 c = __ldcs(&e1[lane + j * 32]);
        float4 vv = s_v[lane + j * 32];
        acc0 = fmaf(a.x, vv.x, acc0);
        acc0 = fmaf(a.y, vv.y, acc0);
        acc0 = fmaf(a.z, vv.z, acc0);
        acc0 = fmaf(a.w, vv.w, acc0);
        acc1 = fmaf(c.x, vv.x, acc1);
        acc1 = fmaf(c.y, vv.y, acc1);
        acc1 = fmaf(c.z, vv.z, acc1);
        acc1 = fmaf(c.w, vv.w, acc1);
    }

#pragma unroll
    for (int o = 16; o > 0; o >>= 1) {
        acc0 += __shfl_down_sync(0xffffffffu, acc0, o);
        acc1 += __shfl_down_sync(0xffffffffu, acc1, o);
    }

    if (lane == 0) {
        g_energy[b * S + s0] = acc0;
        g_energy[b * S + s1] = acc1;
    }
}

// ---------------------------------------------------------------------------
// softmax over s for each b; also re-zeroes g_v[b] for the next replay.
// grid: B blocks of 256 threads, 8 elems/thread (R1-measured best shape).
#define K3_TH 256
__global__ __launch_bounds__(K3_TH) void softmax_kernel(float* __restrict__ out)
{
    __shared__ float red[K3_TH / 32];
    const int b = blockIdx.x;
    const int tid = threadIdx.x;
    const int lane = tid & 31, warp = tid >> 5;
    const float* e = &g_energy[b * S];

    // Re-zero g_v[b,:] (already consumed by energy_kernel this replay).
#pragma unroll
    for (int j = 0; j < H / K3_TH; j++)
        g_v[b * H + tid + j * K3_TH] = 0.0f;

    float vals[S / K3_TH];
    float m = -1e30f;
#pragma unroll
    for (int j = 0; j < S / K3_TH; j++) {
        vals[j] = e[tid + j * K3_TH];
        m = fmaxf(m, vals[j]);
    }
#pragma unroll
    for (int o = 16; o > 0; o >>= 1)
        m = fmaxf(m, __shfl_xor_sync(0xffffffffu, m, o));
    if (lane == 0) red[warp] = m;
    __syncthreads();
#pragma unroll
    for (int w = 0; w < K3_TH / 32; w++) m = fmaxf(m, red[w]);
    __syncthreads();

    float sum = 0.0f;
#pragma unroll
    for (int j = 0; j < S / K3_TH; j++) {
        vals[j] = __expf(vals[j] - m);
        sum += vals[j];
    }
#pragma unroll
    for (int o = 16; o > 0; o >>= 1)
        sum += __shfl_xor_sync(0xffffffffu, sum, o);
    if (lane == 0) red[warp] = sum;
    __syncthreads();
    float total = 0.0f;
#pragma unroll
    for (int w = 0; w < K3_TH / 32; w++) total += red[w];

    const float inv = __frcp_rn(total);
#pragma unroll
    for (int j = 0; j < S / K3_TH; j++)
        out[b * S + tid + j * K3_TH] = vals[j] * inv;
}

// ---------------------------------------------------------------------------
extern "C" void kernel_launch(void* const* d_in, const int* in_sizes, int n_in,
                              void* d_out, int out_size)
{
    const float* dec = (const float*)d_in[0];   // rnn_outputs [1,B,H]
    const float* enc = (const float*)d_in[1];   // encoder_outputs [S,B,H]
    const float* W   = (const float*)d_in[2];   // W_attn [H,H]
    // d_in[3] = b_attn: constant over s per batch -> cancelled by softmax.
    float* out = (float*)d_out;                 // [B,S] float32

    proj_kernel<<<dim3(H / P_HT, H / P_KC, B / P_BT), P_TH>>>(dec, W);
    energy_kernel<<<dim3(S / K2_ROWS, B), 32 * K2_WARPS>>>(enc);
    softmax_kernel<<<B, K3_TH>>>(out);
}